// round 1
// baseline (speedup 1.0000x reference)
#include <cuda_runtime.h>
#include <cstdint>

#define NN 1000000
#define EE 1000000
#define CC 64
#define ROW 65  // C+1 floats per poss_edge row

// Accumulators: 0=sum(mask*logp) 1=sum(mask) 2=sqdiff 3=sum(intrust) 4=raw 5=S
__device__ double g_acc[6];

__global__ void k_zero() {
    if (threadIdx.x < 6) g_acc[threadIdx.x] = 0.0;
}

__global__ void __launch_bounds__(256) k_main(
    const float* __restrict__ pn,      // poss_node [N,64]
    const float* __restrict__ pe,      // poss_edge [E,65]
    const int* __restrict__ gt,        // groundTruth [N]
    const uint8_t* __restrict__ mask,  // mask [N] (bool, 1 byte)
    const int* __restrict__ edges)     // edges [E,2]
{
    const int tid = blockIdx.x * blockDim.x + threadIdx.x;
    const int nthreads = gridDim.x * blockDim.x;

    // ---- node loss: thread-per-node grid-stride ----
    double a_logp = 0.0, a_mask = 0.0;
    for (int i = tid; i < NN; i += nthreads) {
        if (mask[i]) {
            float p = __ldg(&pn[(size_t)i * CC + gt[i]]);
            a_logp += (double)logf(p);
            a_mask += 1.0;
        }
    }

    // ---- edge terms: warp-per-edge grid-stride ----
    const int lane = threadIdx.x & 31;
    const int gw = tid >> 5;
    const int nw = nthreads >> 5;
    double a_sq = 0.0, a_intr = 0.0, a_raw = 0.0, a_S = 0.0;

    for (int e = gw; e < EE; e += nw) {
        int2 ev = ((const int2*)edges)[e];  // uniform across warp -> broadcast
        const float* __restrict__ r0 = pe + (size_t)ev.x * ROW;
        const float* __restrict__ r1 = pe + (size_t)ev.y * ROW;

        // cols [0,64): lanes cover c and c+32 (coalesced)
        float d0 = r0[lane]      - r1[lane];
        float d1 = r0[lane + 32] - r1[lane + 32];
        float s = d0 * d0 + d1 * d1;

        if (lane == 0) {
            // col 64
            float d2 = r0[CC] - r1[CC];
            s += d2 * d2;

            // sequential row e: intrust + edge-label loss
            float plast = pe[(size_t)e * ROW + CC];
            a_intr += (double)plast;

            unsigned m0 = mask[ev.x], m1 = mask[ev.y];
            if (m0 | m1) {
                a_S += 1.0;
                float contrib;
                if (m0 & m1) {
                    int g0 = gt[ev.x], g1 = gt[ev.y];
                    contrib = (g0 == g1) ? logf(pe[(size_t)e * ROW + g0])
                                         : logf(plast);
                } else if (m0) {
                    contrib = logf(plast + pe[(size_t)e * ROW + gt[ev.x]]);
                } else {
                    contrib = logf(plast + pe[(size_t)e * ROW + gt[ev.y]]);
                }
                a_raw -= (double)contrib;
            }
        }
        a_sq += (double)s;
    }

    // ---- block reduction (warp shfl -> smem -> thread 0 -> atomics) ----
    double vals[6] = {a_logp, a_mask, a_sq, a_intr, a_raw, a_S};
    #pragma unroll
    for (int k = 0; k < 6; k++) {
        double v = vals[k];
        #pragma unroll
        for (int o = 16; o; o >>= 1) v += __shfl_xor_sync(0xffffffffu, v, o);
        vals[k] = v;
    }

    __shared__ double sh[8][6];
    const int wib = threadIdx.x >> 5;
    if (lane == 0) {
        #pragma unroll
        for (int k = 0; k < 6; k++) sh[wib][k] = vals[k];
    }
    __syncthreads();
    if (threadIdx.x == 0) {
        const int nwb = blockDim.x >> 5;
        #pragma unroll
        for (int k = 0; k < 6; k++) {
            double t = 0.0;
            for (int w = 0; w < nwb; w++) t += sh[w][k];
            atomicAdd(&g_acc[k], t);
        }
    }
}

__global__ void k_final(float* __restrict__ out) {
    double loss = -g_acc[0] / g_acc[1];
    double semi = 0.5 * ((double)EE - g_acc[3]) * g_acc[2];   // SEMI_LAMBDA = 0.5
    double S    = g_acc[5];
    double edge = g_acc[4] / (S * S);                          // EDGE_LAMBDA^2 = 1
    out[0] = (float)(loss + semi + edge);
}

extern "C" void kernel_launch(void* const* d_in, const int* in_sizes, int n_in,
                              void* d_out, int out_size) {
    const float*   pn    = (const float*)d_in[0];
    const float*   pe    = (const float*)d_in[1];
    const int*     gt    = (const int*)d_in[2];
    const uint8_t* mask  = (const uint8_t*)d_in[3];
    const int*     edges = (const int*)d_in[4];
    float* out = (float*)d_out;

    k_zero<<<1, 32>>>();
    k_main<<<1184, 256>>>(pn, pe, gt, mask, edges);
    k_final<<<1, 1>>>(out);
}

// round 2
// speedup vs baseline: 1.5471x; 1.5471x over previous
#include <cuda_runtime.h>
#include <cstdint>

#define NN 1000000
#define EE 1000000
#define CC 64
#define ROW 65  // C+1 floats per poss_edge row

// Accumulators: 0=sum(mask*logp) 1=sum(mask) 2=sqdiff 3=sum(intrust) 4=raw 5=S
__device__ double g_acc[6];

__global__ void k_zero() {
    if (threadIdx.x < 6) g_acc[threadIdx.x] = 0.0;
}

struct Acc {
    double logp, maskn, sq, intr, raw, S;
};

// ---- node loss: thread-per-node ----
__device__ __forceinline__ void phase_node(
    const float* __restrict__ pn, const int* __restrict__ gt,
    const uint8_t* __restrict__ mask, int tid, int nth, Acc& a)
{
    for (int i = tid; i < NN; i += nth) {
        if (mask[i]) {
            a.logp += (double)__logf(__ldg(&pn[(size_t)i * CC + gt[i]]));
            a.maskn += 1.0;
        }
    }
}

// ---- per-edge scalar terms (intrust, edge-label loss): thread-per-edge ----
__device__ __forceinline__ void phase_scalar(
    const float* __restrict__ pe, const int* __restrict__ gt,
    const uint8_t* __restrict__ mask, const int2* __restrict__ edges2,
    int tid, int nth, Acc& a)
{
    for (int e = tid; e < EE; e += nth) {
        int2 ev = edges2[e];
        float plast = __ldg(&pe[(size_t)e * ROW + CC]);
        a.intr += (double)plast;
        unsigned m0 = mask[ev.x], m1 = mask[ev.y];
        if (m0 | m1) {
            a.S += 1.0;
            float c;
            if (m0 & m1) {
                int g0 = gt[ev.x], g1 = gt[ev.y];
                c = (g0 == g1) ? __logf(__ldg(&pe[(size_t)e * ROW + g0]))
                               : __logf(plast);
            } else {
                int g = m0 ? gt[ev.x] : gt[ev.y];
                c = __logf(plast + __ldg(&pe[(size_t)e * ROW + g]));
            }
            a.raw -= (double)c;
        }
    }
}

// ---- sqdiff: warp-per-4-edges, MLP=16 row loads in flight ----
__device__ __forceinline__ void phase_sq(
    const float* __restrict__ pe, const int2* __restrict__ edges2,
    int gw, int nw, int lane, Acc& a)
{
    const int G = EE / 4;
    for (int g = gw; g < G; g += nw) {
        const int e0 = g * 4;
        int2 ev[4];
        #pragma unroll
        for (int j = 0; j < 4; j++) ev[j] = edges2[e0 + j];

        const float* ra[4];
        const float* rb[4];
        #pragma unroll
        for (int j = 0; j < 4; j++) {
            ra[j] = pe + (size_t)ev[j].x * ROW;
            rb[j] = pe + (size_t)ev[j].y * ROW;
        }

        // issue all 16 gather loads before consuming any
        float va[4], wa[4], vb[4], wb[4];
        #pragma unroll
        for (int j = 0; j < 4; j++) {
            va[j] = ra[j][lane];
            wa[j] = ra[j][lane + 32];
            vb[j] = rb[j][lane];
            wb[j] = rb[j][lane + 32];
        }

        float s = 0.0f;
        #pragma unroll
        for (int j = 0; j < 4; j++) {
            float d0 = va[j] - vb[j];
            float d1 = wa[j] - wb[j];
            s += d0 * d0 + d1 * d1;
        }
        // col 64 residual: lane j handles edge j (no lane-0 hotspot)
        if (lane < 4) {
            float d2 = ra[lane][CC] - rb[lane][CC];
            s += d2 * d2;
        }
        a.sq += (double)s;  // one DADD per 4 edges per lane
    }
}

__global__ void __launch_bounds__(256) k_main(
    const float* __restrict__ pn,
    const float* __restrict__ pe,
    const int* __restrict__ gt,
    const uint8_t* __restrict__ mask,
    const int* __restrict__ edges)
{
    const int tid = blockIdx.x * blockDim.x + threadIdx.x;
    const int nth = gridDim.x * blockDim.x;
    const int lane = threadIdx.x & 31;
    const int gw = tid >> 5;
    const int nw = nth >> 5;
    const int2* edges2 = (const int2*)edges;

    Acc a = {0.0, 0.0, 0.0, 0.0, 0.0, 0.0};

    // parity ordering: half the blocks run the BW-bound phase first so the
    // latency-bound phases overlap with it chip-wide
    if (blockIdx.x & 1) {
        phase_sq(pe, edges2, gw, nw, lane, a);
        phase_scalar(pe, gt, mask, edges2, tid, nth, a);
        phase_node(pn, gt, mask, tid, nth, a);
    } else {
        phase_node(pn, gt, mask, tid, nth, a);
        phase_scalar(pe, gt, mask, edges2, tid, nth, a);
        phase_sq(pe, edges2, gw, nw, lane, a);
    }

    // ---- block reduction (warp shfl -> smem -> thread 0 -> atomics) ----
    double vals[6] = {a.logp, a.maskn, a.sq, a.intr, a.raw, a.S};
    #pragma unroll
    for (int k = 0; k < 6; k++) {
        double v = vals[k];
        #pragma unroll
        for (int o = 16; o; o >>= 1) v += __shfl_xor_sync(0xffffffffu, v, o);
        vals[k] = v;
    }

    __shared__ double sh[8][6];
    const int wib = threadIdx.x >> 5;
    if (lane == 0) {
        #pragma unroll
        for (int k = 0; k < 6; k++) sh[wib][k] = vals[k];
    }
    __syncthreads();
    if (threadIdx.x == 0) {
        const int nwb = blockDim.x >> 5;
        #pragma unroll
        for (int k = 0; k < 6; k++) {
            double t = 0.0;
            for (int w = 0; w < nwb; w++) t += sh[w][k];
            atomicAdd(&g_acc[k], t);
        }
    }
}

__global__ void k_final(float* __restrict__ out) {
    double loss = -g_acc[0] / g_acc[1];
    double semi = 0.5 * ((double)EE - g_acc[3]) * g_acc[2];   // SEMI_LAMBDA = 0.5
    double S    = g_acc[5];
    double edge = g_acc[4] / (S * S);                          // EDGE_LAMBDA^2 = 1
    out[0] = (float)(loss + semi + edge);
}

extern "C" void kernel_launch(void* const* d_in, const int* in_sizes, int n_in,
                              void* d_out, int out_size) {
    const float*   pn    = (const float*)d_in[0];
    const float*   pe    = (const float*)d_in[1];
    const int*     gt    = (const int*)d_in[2];
    const uint8_t* mask  = (const uint8_t*)d_in[3];
    const int*     edges = (const int*)d_in[4];
    float* out = (float*)d_out;

    k_zero<<<1, 32>>>();
    k_main<<<1184, 256>>>(pn, pe, gt, mask, edges);
    k_final<<<1, 1>>>(out);
}

// round 3
// speedup vs baseline: 2.3423x; 1.5140x over previous
#include <cuda_runtime.h>
#include <cstdint>

#define NN 1000000
#define EE 1000000
#define CC 64
#define ROW 65           // C+1 floats per poss_edge row
#define GRID 592         // 4 blocks/SM * 148 SMs -> single wave
#define NODE_B 64
#define SCALAR_B 160
#define GROUPS (EE / 4)  // 250000 groups of 4 edges
#define CHUNK 128        // groups per steal
#define NCHUNK ((GROUPS + CHUNK - 1) / CHUNK)

// Accumulators: 0=sum(mask*logp) 1=sum(mask) 2=sqdiff 3=sum(intrust) 4=raw 5=S
__device__ double g_acc[6];
__device__ int g_counter;

__global__ void k_zero() {
    if (threadIdx.x < 6) g_acc[threadIdx.x] = 0.0;
    if (threadIdx.x == 0) g_counter = 0;
}

__global__ void __launch_bounds__(256, 4) k_main(
    const float* __restrict__ pn,
    const float* __restrict__ pe,
    const int* __restrict__ gt,
    const uint8_t* __restrict__ mask,
    const int* __restrict__ edges)
{
    const int bid = blockIdx.x;
    const int lane = threadIdx.x & 31;
    const int wib = threadIdx.x >> 5;
    const int2* __restrict__ edges2 = (const int2*)edges;

    float f_logp = 0.0f, f_intr = 0.0f, f_raw = 0.0f, f_sq = 0.0f;
    int i_mask = 0, i_S = 0;

    if (bid < NODE_B) {
        // ---- node loss: ILP-4 thread-per-node over a private sub-grid ----
        const int ltid = bid * 256 + threadIdx.x;
        const int lnth = NODE_B * 256;
        int i = ltid;
        for (; i + 3 * lnth < NN; i += 4 * lnth) {
            int idx[4];
            unsigned m[4];
            int g[4];
            #pragma unroll
            for (int j = 0; j < 4; j++) idx[j] = i + j * lnth;
            #pragma unroll
            for (int j = 0; j < 4; j++) m[j] = mask[idx[j]];
            #pragma unroll
            for (int j = 0; j < 4; j++) g[j] = gt[idx[j]];
            float p[4];
            #pragma unroll
            for (int j = 0; j < 4; j++)
                p[j] = m[j] ? __ldcs(&pn[(size_t)idx[j] * CC + g[j]]) : 1.0f;
            #pragma unroll
            for (int j = 0; j < 4; j++) {
                if (m[j]) { f_logp += __logf(p[j]); i_mask++; }
            }
        }
        for (; i < NN; i += lnth) {
            if (mask[i]) {
                f_logp += __logf(__ldcs(&pn[(size_t)i * CC + gt[i]]));
                i_mask++;
            }
        }
    } else if (bid < NODE_B + SCALAR_B) {
        // ---- per-edge scalar terms: ILP-4 thread-per-edge ----
        const int ltid = (bid - NODE_B) * 256 + threadIdx.x;
        const int lnth = SCALAR_B * 256;
        int e = ltid;
        for (; e + 3 * lnth < EE; e += 4 * lnth) {
            int ei[4];
            int2 ev[4];
            float pl[4];
            unsigned m0[4], m1[4];
            int g0[4], g1[4];
            #pragma unroll
            for (int j = 0; j < 4; j++) ei[j] = e + j * lnth;
            #pragma unroll
            for (int j = 0; j < 4; j++) ev[j] = edges2[ei[j]];
            #pragma unroll
            for (int j = 0; j < 4; j++) pl[j] = pe[(size_t)ei[j] * ROW + CC];
            #pragma unroll
            for (int j = 0; j < 4; j++) { m0[j] = mask[ev[j].x]; m1[j] = mask[ev[j].y]; }
            #pragma unroll
            for (int j = 0; j < 4; j++) { g0[j] = gt[ev[j].x]; g1[j] = gt[ev[j].y]; }
            #pragma unroll
            for (int j = 0; j < 4; j++) {
                f_intr += pl[j];
                if (m0[j] | m1[j]) {
                    i_S++;
                    float c;
                    if (m0[j] & m1[j]) {
                        c = (g0[j] == g1[j])
                              ? __logf(pe[(size_t)ei[j] * ROW + g0[j]])
                              : __logf(pl[j]);
                    } else {
                        int g = m0[j] ? g0[j] : g1[j];
                        c = __logf(pl[j] + pe[(size_t)ei[j] * ROW + g]);
                    }
                    f_raw -= c;
                }
            }
        }
        for (; e < EE; e += lnth) {
            int2 ev = edges2[e];
            float pl = pe[(size_t)e * ROW + CC];
            f_intr += pl;
            unsigned m0 = mask[ev.x], m1 = mask[ev.y];
            if (m0 | m1) {
                i_S++;
                float c;
                if (m0 & m1) {
                    int ga = gt[ev.x], gb = gt[ev.y];
                    c = (ga == gb) ? __logf(pe[(size_t)e * ROW + ga]) : __logf(pl);
                } else {
                    int g = m0 ? gt[ev.x] : gt[ev.y];
                    c = __logf(pl + pe[(size_t)e * ROW + g]);
                }
                f_raw -= c;
            }
        }
    }

    // ---- sqdiff: warp-per-4-edges, work-stolen chunks; all blocks join ----
    __shared__ int s_chunk;
    for (;;) {
        if (threadIdx.x == 0) s_chunk = atomicAdd(&g_counter, 1);
        __syncthreads();
        const int c = s_chunk;
        __syncthreads();
        if (c >= NCHUNK) break;
        const int gbeg = c * CHUNK;
        const int gend = (gbeg + CHUNK < GROUPS) ? gbeg + CHUNK : GROUPS;
        for (int g = gbeg + wib; g < gend; g += 8) {
            const int e0 = g * 4;
            int2 ev[4];
            #pragma unroll
            for (int j = 0; j < 4; j++) ev[j] = edges2[e0 + j];

            const float* ra[4];
            const float* rb[4];
            #pragma unroll
            for (int j = 0; j < 4; j++) {
                ra[j] = pe + (size_t)ev[j].x * ROW;
                rb[j] = pe + (size_t)ev[j].y * ROW;
            }

            // issue all 16 gather loads before consuming any
            float va[4], wa[4], vb[4], wb[4];
            #pragma unroll
            for (int j = 0; j < 4; j++) {
                va[j] = ra[j][lane];
                wa[j] = ra[j][lane + 32];
                vb[j] = rb[j][lane];
                wb[j] = rb[j][lane + 32];
            }

            float s = 0.0f;
            #pragma unroll
            for (int j = 0; j < 4; j++) {
                float d0 = va[j] - vb[j];
                float d1 = wa[j] - wb[j];
                s += d0 * d0 + d1 * d1;
            }
            if (lane < 4) {
                float d2 = ra[lane][CC] - rb[lane][CC];
                s += d2 * d2;
            }
            f_sq += s;
        }
    }

    // ---- block reduction (warp shfl -> smem -> thread 0 -> atomics) ----
    double vals[6] = {(double)f_logp, (double)i_mask, (double)f_sq,
                      (double)f_intr, (double)f_raw,  (double)i_S};
    #pragma unroll
    for (int k = 0; k < 6; k++) {
        double v = vals[k];
        #pragma unroll
        for (int o = 16; o; o >>= 1) v += __shfl_xor_sync(0xffffffffu, v, o);
        vals[k] = v;
    }

    __shared__ double sh[8][6];
    if (lane == 0) {
        #pragma unroll
        for (int k = 0; k < 6; k++) sh[wib][k] = vals[k];
    }
    __syncthreads();
    if (threadIdx.x == 0) {
        #pragma unroll
        for (int k = 0; k < 6; k++) {
            double t = 0.0;
            for (int w = 0; w < 8; w++) t += sh[w][k];
            atomicAdd(&g_acc[k], t);
        }
    }
}

__global__ void k_final(float* __restrict__ out) {
    double loss = -g_acc[0] / g_acc[1];
    double semi = 0.5 * ((double)EE - g_acc[3]) * g_acc[2];   // SEMI_LAMBDA = 0.5
    double S    = g_acc[5];
    double edge = g_acc[4] / (S * S);                          // EDGE_LAMBDA^2 = 1
    out[0] = (float)(loss + semi + edge);
}

extern "C" void kernel_launch(void* const* d_in, const int* in_sizes, int n_in,
                              void* d_out, int out_size) {
    const float*   pn    = (const float*)d_in[0];
    const float*   pe    = (const float*)d_in[1];
    const int*     gt    = (const int*)d_in[2];
    const uint8_t* mask  = (const uint8_t*)d_in[3];
    const int*     edges = (const int*)d_in[4];
    float* out = (float*)d_out;

    k_zero<<<1, 32>>>();
    k_main<<<GRID, 256>>>(pn, pe, gt, mask, edges);
    k_final<<<1, 1>>>(out);
}